// round 16
// baseline (speedup 1.0000x reference)
#include <cuda_runtime.h>
#include <cuda_fp16.h>
#include <cstdint>
#include <math.h>

// Problem constants
#define B_ 8
#define N_ 2048
#define D_ 512
#define E_ 512

static constexpr long QKV_ELEMS  = (long)B_ * N_ * D_;   // 8,388,608
static constexpr long W_ELEMS    = (long)E_ * D_;        // 262,144
static constexpr long ATTN_ELEMS = (long)B_ * N_ * N_;   // 33,554,432

// ---------------- scratch (static device arrays; allocation-guard safe) ----
__device__ __half g_q16[QKV_ELEMS], g_k16[QKV_ELEMS], g_v16[QKV_ELEMS];
__device__ __half g_Wq16t[W_ELEMS];                       // Wq^T [d][e]
__device__ __half g_Wk16t[W_ELEMS];                       // Wk^T [d][e]
__device__ __half g_Wv16[W_ELEMS];                        // Wv   [e][d]
__device__ __half g_Gt[W_ELEMS];                          // Gt[d'][d] = (Wq^T Wk)_{d,d'} * c^2 s
__device__ __half g_tmp[QKV_ELEMS];                       // tmp = q @ G'
__device__ __half g_vpth[QKV_ELEMS];                      // v-proj fp16, [b][e][n]
__device__ __half g_ah[ATTN_ELEMS];                       // attn fp16

// ---------------- PTX helpers ----------------------------------------------
__device__ __forceinline__ uint32_t smem_to_u32(const void* p) {
    uint32_t a;
    asm("{ .reg .u64 t; cvta.to.shared.u64 t, %1; cvt.u32.u64 %0, t; }" : "=r"(a) : "l"(p));
    return a;
}

#define CP_ASYNC16(smem_u32, gptr) \
    asm volatile("cp.async.cg.shared.global [%0], [%1], 16;" :: "r"(smem_u32), "l"(gptr) : "memory")
#define CP_ASYNC_COMMIT() asm volatile("cp.async.commit_group;" ::: "memory")
#define CP_ASYNC_WAIT1()  asm volatile("cp.async.wait_group 1;" ::: "memory")
#define CP_ASYNC_WAIT2()  asm volatile("cp.async.wait_group 2;" ::: "memory")

__device__ __forceinline__ void ldsm_x4(uint32_t* r, uint32_t addr) {
    asm volatile("ldmatrix.sync.aligned.m8n8.x4.shared.b16 {%0,%1,%2,%3}, [%4];"
        : "=r"(r[0]), "=r"(r[1]), "=r"(r[2]), "=r"(r[3]) : "r"(addr));
}

__device__ __forceinline__ void mma16816(float* c, const uint32_t* a, const uint32_t* b) {
    asm volatile(
        "mma.sync.aligned.m16n8k16.row.col.f32.f16.f16.f32 "
        "{%0,%1,%2,%3}, {%4,%5,%6,%7}, {%8,%9}, {%0,%1,%2,%3};"
        : "+f"(c[0]), "+f"(c[1]), "+f"(c[2]), "+f"(c[3])
        : "r"(a[0]), "r"(a[1]), "r"(a[2]), "r"(a[3]), "r"(b[0]), "r"(b[1]));
}

// fp16-accumulator MMAs (accumulate one K=32 slab in fp16, then promote)
__device__ __forceinline__ void mma16816h_init(uint32_t* d, const uint32_t* a, const uint32_t* b) {
    asm volatile(
        "mma.sync.aligned.m16n8k16.row.col.f16.f16.f16.f16 "
        "{%0,%1}, {%2,%3,%4,%5}, {%6,%7}, {%8,%9};"
        : "=r"(d[0]), "=r"(d[1])
        : "r"(a[0]), "r"(a[1]), "r"(a[2]), "r"(a[3]), "r"(b[0]), "r"(b[1]),
          "r"(0u), "r"(0u));
}
__device__ __forceinline__ void mma16816h_acc(uint32_t* d, const uint32_t* a, const uint32_t* b) {
    asm volatile(
        "mma.sync.aligned.m16n8k16.row.col.f16.f16.f16.f16 "
        "{%0,%1}, {%2,%3,%4,%5}, {%6,%7}, {%0,%1};"
        : "+r"(d[0]), "+r"(d[1])
        : "r"(a[0]), "r"(a[1]), "r"(a[2]), "r"(a[3]), "r"(b[0]), "r"(b[1]));
}

// ---------------------------------------------------------------------------
// fp32-acc single-product GEMM core (proven R13 config):
// tile 128x128, BK=32, 8 warps (64x32), 3-stage ring, 2 CTAs/SM.
// ---------------------------------------------------------------------------
#define BKH 32
#define ROWH 40
#define ROWB 80
#define T_TILE_B (128 * ROWB)
#define STAGE_B (2 * T_TILE_B)
#define OFF_B (T_TILE_B)
#define NSTAGE 3
#define GEMM_SMEM_TOTAL (NSTAGE * STAGE_B)  // 61440 -> 2 CTAs/SM
#define O_NSTAGE 4
#define O_SMEM_TOTAL (O_NSTAGE * STAGE_B)   // 81920 -> 1 CTA/SM

__device__ __forceinline__ void gemm_core(
    const __half* __restrict__ A, const __half* __restrict__ B,
    int M, int N, int K, float alpha, int mode,
    void* __restrict__ C0, uint32_t smem_base)
{
    const int tid  = threadIdx.x;
    const int wid  = tid >> 5;
    const int lane = tid & 31;
    const int wm = wid & 1;
    const int wn = wid >> 1;

    const int m0 = blockIdx.y * 128;
    const int n0 = blockIdx.x * 128;

    float acc[4][4][4];
    #pragma unroll
    for (int i = 0; i < 4; i++)
        #pragma unroll
        for (int j = 0; j < 4; j++)
            #pragma unroll
            for (int c = 0; c < 4; c++) acc[i][j][c] = 0.0f;

    const int nslab = K / BKH;
    const int lrow = tid >> 2;
    const int lch  = tid & 3;

    auto load_slab = [&](int s) {
        const long koff = (long)s * BKH + lch * 8;
        const uint32_t st = smem_base + (uint32_t)(s % NSTAGE) * STAGE_B;
        const uint32_t so = (uint32_t)(lrow * ROWB + lch * 16);
        #pragma unroll
        for (int i = 0; i < 2; i++) {
            const int r = lrow + 64 * i;
            const long ga = (long)(m0 + r) * K + koff;
            const long gb = (long)(n0 + r) * K + koff;
            const uint32_t ro = so + (uint32_t)i * (64 * ROWB);
            CP_ASYNC16(st +         ro, A + ga);
            CP_ASYNC16(st + OFF_B + ro, B + gb);
        }
    };

    load_slab(0); CP_ASYNC_COMMIT();
    if (nslab > 1) load_slab(1);
    CP_ASYNC_COMMIT();

    const int am = lane & 15;
    const int ac = (lane >> 4) << 3;
    const int bn = ((lane >> 4) << 3) + (lane & 7);
    const int bc = ((lane >> 3) & 1) << 3;

    for (int s = 0; s < nslab; s++) {
        CP_ASYNC_WAIT1();
        __syncthreads();

        const uint32_t st = smem_base + (uint32_t)(s % NSTAGE) * STAGE_B;
        #pragma unroll
        for (int k16 = 0; k16 < 2; k16++) {
            uint32_t ra[4][4];
            #pragma unroll
            for (int mi = 0; mi < 4; mi++) {
                const uint32_t ao =
                    (uint32_t)((wm * 64 + mi * 16 + am) * ROWH + k16 * 16 + ac) * 2;
                ldsm_x4(ra[mi], st + ao);
            }
            uint32_t th[2][4];
            const uint32_t bbase =
                (uint32_t)((wn * 32 + bn) * ROWH + k16 * 16 + bc) * 2;
            ldsm_x4(th[0], st + OFF_B + bbase);

            if (k16 == 0) {
                if (s + 2 < nslab) load_slab(s + 2);
                CP_ASYNC_COMMIT();
            }

            #pragma unroll
            for (int pair = 0; pair < 2; pair++) {
                const int cur = pair & 1;
                if (pair < 1) {
                    const uint32_t bo = bbase + (uint32_t)(16 * ROWH) * 2;
                    ldsm_x4(th[cur ^ 1], st + OFF_B + bo);
                }
                #pragma unroll
                for (int nj = 0; nj < 2; nj++) {
                    const uint32_t bh2[2] = { th[cur][nj * 2], th[cur][nj * 2 + 1] };
                    #pragma unroll
                    for (int mi = 0; mi < 4; mi++)
                        mma16816(acc[mi][pair * 2 + nj], ra[mi], bh2);
                }
            }
        }
    }

    const int rq = lane >> 2;
    const int cq = (lane & 3) * 2;
    #pragma unroll
    for (int mi = 0; mi < 4; mi++) {
        #pragma unroll
        for (int ni = 0; ni < 4; ni++) {
            const int mA = m0 + wm * 64 + mi * 16 + rq;
            const int mB = mA + 8;
            const int n  = n0 + wn * 32 + ni * 8 + cq;
            const float v0 = acc[mi][ni][0] * alpha;
            const float v1 = acc[mi][ni][1] * alpha;
            const float v2 = acc[mi][ni][2] * alpha;
            const float v3 = acc[mi][ni][3] * alpha;
            if (mode == 0) {
                float* Cf = (float*)C0;
                *(float2*)(Cf + (size_t)mA * N + n) = make_float2(v0, v1);
                *(float2*)(Cf + (size_t)mB * N + n) = make_float2(v2, v3);
            } else if (mode == 4) {
                *(__half2*)((__half*)C0 + (size_t)mA * N + n) =
                    __halves2half2(__float2half_rn(v0), __float2half_rn(v1));
                *(__half2*)((__half*)C0 + (size_t)mB * N + n) =
                    __halves2half2(__float2half_rn(v2), __float2half_rn(v3));
            } else {
                const float vv[4] = { v0, v1, v2, v3 };
                #pragma unroll
                for (int e = 0; e < 4; e++) {
                    const int m = (e < 2) ? mA : mB;
                    const int nn2 = n + (e & 1);
                    const int bi = m >> 11;
                    const int mm = m & (N_ - 1);
                    const size_t idx = ((size_t)bi * E_ + nn2) * N_ + mm;
                    ((__half*)C0)[idx] = __float2half_rn(vv[e]);
                }
            }
        }
    }
}

__global__ __launch_bounds__(256, 2) void gemm_s(
    const __half* __restrict__ A, const __half* __restrict__ B,
    int M, int N, int K, float alpha, int mode, void* __restrict__ C0)
{
    extern __shared__ char smem[];
    gemm_core(A, B, M, N, K, alpha, mode, C0, smem_to_u32(smem));
}

// batched fp32-acc GEMM (dots)
__global__ __launch_bounds__(256, 2) void gemm_b(
    const __half* __restrict__ A, const __half* __restrict__ B,
    int M, int N, int K, long sA, long sB, long sC,
    float alpha, void* __restrict__ C0)
{
    extern __shared__ char smem[];
    const int z = blockIdx.z;
    gemm_core(A + (long)z * sA, B + (long)z * sB, M, N, K, alpha, 0,
              (float*)C0 + (size_t)z * sC, smem_to_u32(smem));
}

// merged: z = 0 (tmp = q16 @ Gt^T, mode 4), z = 1 (v-proj, mode 2 transposed)
__global__ __launch_bounds__(256, 2) void gemm_proj(
    const __half* __restrict__ q16, const __half* __restrict__ v16,
    const __half* __restrict__ Gt, const __half* __restrict__ Wv,
    __half* __restrict__ tmp, __half* __restrict__ vpth, float c_eq)
{
    extern __shared__ char smem[];
    const int z = blockIdx.z;
    const __half* A = (z == 0) ? q16 : v16;
    const __half* B = (z == 0) ? Gt  : Wv;
    void* C = (z == 0) ? (void*)tmp : (void*)vpth;
    const int mode = (z == 0) ? 4 : 2;
    const float alpha = (z == 0) ? 1.0f : c_eq;
    gemm_core(A, B, B_ * N_, E_, D_, alpha, mode, C, smem_to_u32(smem));
}

// ---------------------------------------------------------------------------
// out GEMM with per-slab fp16 accumulation (tests the 2x fp16-acc hypothesis):
// acc_h accumulates one K=32 slab (2 MMAs, first with C=0), then promoted to
// fp32 acc via FADD. 1 CTA/SM, 4-stage cp.async ring. Batched via blockIdx.z.
// C fp32 [M,N].
// ---------------------------------------------------------------------------
__global__ __launch_bounds__(256, 1) void gemm_o(
    const __half* __restrict__ A, const __half* __restrict__ B,
    int M, int N, int K, long sA, long sB, long sC,
    void* __restrict__ C0)
{
    extern __shared__ char smem[];
    const uint32_t smem_base = smem_to_u32(smem);
    const int tid  = threadIdx.x;
    const int wid  = tid >> 5;
    const int lane = tid & 31;
    const int wm = wid & 1;
    const int wn = wid >> 1;
    const int z = blockIdx.z;

    A += (long)z * sA;
    B += (long)z * sB;
    float* Cf = (float*)C0 + (size_t)z * sC;

    const int m0 = blockIdx.y * 128;
    const int n0 = blockIdx.x * 128;

    float acc[4][4][4];
    #pragma unroll
    for (int i = 0; i < 4; i++)
        #pragma unroll
        for (int j = 0; j < 4; j++)
            #pragma unroll
            for (int c = 0; c < 4; c++) acc[i][j][c] = 0.0f;

    uint32_t acch[4][4][2];

    const int nslab = K / BKH;
    const int lrow = tid >> 2;
    const int lch  = tid & 3;

    auto load_slab = [&](int s) {
        const long koff = (long)s * BKH + lch * 8;
        const uint32_t st = smem_base + (uint32_t)(s % O_NSTAGE) * STAGE_B;
        const uint32_t so = (uint32_t)(lrow * ROWB + lch * 16);
        #pragma unroll
        for (int i = 0; i < 2; i++) {
            const int r = lrow + 64 * i;
            const long ga = (long)(m0 + r) * K + koff;
            const long gb = (long)(n0 + r) * K + koff;
            const uint32_t ro = so + (uint32_t)i * (64 * ROWB);
            CP_ASYNC16(st +         ro, A + ga);
            CP_ASYNC16(st + OFF_B + ro, B + gb);
        }
    };

    load_slab(0); CP_ASYNC_COMMIT();
    load_slab(1); CP_ASYNC_COMMIT();
    load_slab(2); CP_ASYNC_COMMIT();

    const int am = lane & 15;
    const int ac = (lane >> 4) << 3;
    const int bn = ((lane >> 4) << 3) + (lane & 7);
    const int bc = ((lane >> 3) & 1) << 3;

    for (int s = 0; s < nslab; s++) {
        CP_ASYNC_WAIT2();
        __syncthreads();

        const uint32_t st = smem_base + (uint32_t)(s % O_NSTAGE) * STAGE_B;
        #pragma unroll
        for (int k16 = 0; k16 < 2; k16++) {
            uint32_t ra[4][4];
            #pragma unroll
            for (int mi = 0; mi < 4; mi++) {
                const uint32_t ao =
                    (uint32_t)((wm * 64 + mi * 16 + am) * ROWH + k16 * 16 + ac) * 2;
                ldsm_x4(ra[mi], st + ao);
            }
            uint32_t th[2][4];
            const uint32_t bbase =
                (uint32_t)((wn * 32 + bn) * ROWH + k16 * 16 + bc) * 2;
            ldsm_x4(th[0], st + OFF_B + bbase);

            if (k16 == 0) {
                if (s + 3 < nslab) load_slab(s + 3);
                CP_ASYNC_COMMIT();
            }

            #pragma unroll
            for (int pair = 0; pair < 2; pair++) {
                const int cur = pair & 1;
                if (pair < 1) {
                    const uint32_t bo = bbase + (uint32_t)(16 * ROWH) * 2;
                    ldsm_x4(th[cur ^ 1], st + OFF_B + bo);
                }
                #pragma unroll
                for (int nj = 0; nj < 2; nj++) {
                    const uint32_t bh2[2] = { th[cur][nj * 2], th[cur][nj * 2 + 1] };
                    #pragma unroll
                    for (int mi = 0; mi < 4; mi++) {
                        if (k16 == 0) mma16816h_init(acch[mi][pair * 2 + nj], ra[mi], bh2);
                        else          mma16816h_acc (acch[mi][pair * 2 + nj], ra[mi], bh2);
                    }
                }
            }
        }
        // promote slab's fp16 partial sums into fp32 accumulators
        #pragma unroll
        for (int mi = 0; mi < 4; mi++)
            #pragma unroll
            for (int ni = 0; ni < 4; ni++) {
                const float2 lo = __half22float2(*(__half2*)&acch[mi][ni][0]);
                const float2 hi = __half22float2(*(__half2*)&acch[mi][ni][1]);
                acc[mi][ni][0] += lo.x;
                acc[mi][ni][1] += lo.y;
                acc[mi][ni][2] += hi.x;
                acc[mi][ni][3] += hi.y;
            }
    }

    const int rq = lane >> 2;
    const int cq = (lane & 3) * 2;
    #pragma unroll
    for (int mi = 0; mi < 4; mi++) {
        #pragma unroll
        for (int ni = 0; ni < 4; ni++) {
            const int mA = m0 + wm * 64 + mi * 16 + rq;
            const int mB = mA + 8;
            const int n  = n0 + wn * 32 + ni * 8 + cq;
            *(float2*)(Cf + (size_t)mA * N + n) = make_float2(acc[mi][ni][0], acc[mi][ni][1]);
            *(float2*)(Cf + (size_t)mB * N + n) = make_float2(acc[mi][ni][2], acc[mi][ni][3]);
        }
    }
}

// ---------------------------------------------------------------------------
// elementwise conversions
// ---------------------------------------------------------------------------
__global__ __launch_bounds__(256) void conv3(
    const float* __restrict__ x0, const float* __restrict__ x1, const float* __restrict__ x2,
    __half* __restrict__ h0, __half* __restrict__ h1, __half* __restrict__ h2, long n4)
{
    const int zz = blockIdx.z;
    const float* x = (zz == 0) ? x0 : (zz == 1) ? x1 : x2;
    __half* h = (zz == 0) ? h0 : (zz == 1) ? h1 : h2;
    for (long i = blockIdx.x * 256 + threadIdx.x; i < n4; i += (long)gridDim.x * 256) {
        float4 vv = ((const float4*)x)[i];
        __half2* hp = (__half2*)(h + i * 4);
        hp[0] = __halves2half2(__float2half_rn(vv.x), __float2half_rn(vv.y));
        hp[1] = __halves2half2(__float2half_rn(vv.z), __float2half_rn(vv.w));
    }
}

__global__ __launch_bounds__(256) void conv_wt(
    const float* __restrict__ Wq, const float* __restrict__ Wk, const float* __restrict__ Wv,
    __half* __restrict__ Wqt, __half* __restrict__ Wkt, __half* __restrict__ Wv16)
{
    const int zz = blockIdx.z;
    const float* x = (zz == 0) ? Wq : (zz == 1) ? Wk : Wv;
    __half* o = (zz == 0) ? Wqt : (zz == 1) ? Wkt : Wv16;
    for (long i = blockIdx.x * 256 + threadIdx.x; i < W_ELEMS; i += (long)gridDim.x * 256) {
        const int e = (int)(i >> 9);
        const int d = (int)(i & 511);
        const __half h = __float2half_rn(x[i]);
        if (zz < 2) o[(size_t)d * E_ + e] = h;
        else        o[i] = h;
    }
}

// ---------------------------------------------------------------------------
// fused softmax (in place, fp32) + fp16 emission. One block per row.
// ---------------------------------------------------------------------------
__global__ __launch_bounds__(256) void softmax_fused(
    float* __restrict__ attn, __half* __restrict__ ah)
{
    const size_t row = blockIdx.x;
    float* p = attn + row * N_;
    const int t = threadIdx.x;
    __shared__ float red[8];

    float4 va = ((const float4*)p)[t];
    float4 vb = ((const float4*)p)[t + 256];

    float vmax = fmaxf(fmaxf(fmaxf(va.x, va.y), fmaxf(va.z, va.w)),
                       fmaxf(fmaxf(vb.x, vb.y), fmaxf(vb.z, vb.w)));
    #pragma unroll
    for (int o = 16; o > 0; o >>= 1) vmax = fmaxf(vmax, __shfl_xor_sync(0xFFFFFFFF, vmax, o));
    if ((t & 31) == 0) red[t >> 5] = vmax;
    __syncthreads();
    float m = fmaxf(fmaxf(fmaxf(red[0], red[1]), fmaxf(red[2], red[3])),
                    fmaxf(fmaxf(red[4], red[5]), fmaxf(red[6], red[7])));
    __syncthreads();

    va.x = __expf(va.x - m); va.y = __expf(va.y - m); va.z = __expf(va.z - m); va.w = __expf(va.w - m);
    vb.x = __expf(vb.x - m); vb.y = __expf(vb.y - m); vb.z = __expf(vb.z - m); vb.w = __expf(vb.w - m);

    float sum = va.x + va.y + va.z + va.w + vb.x + vb.y + vb.z + vb.w;
    #pragma unroll
    for (int o = 16; o > 0; o >>= 1) sum += __shfl_xor_sync(0xFFFFFFFF, sum, o);
    if ((t & 31) == 0) red[t >> 5] = sum;
    __syncthreads();
    const float inv = 1.0f / (red[0] + red[1] + red[2] + red[3] + red[4] + red[5] + red[6] + red[7]);

    va.x *= inv; va.y *= inv; va.z *= inv; va.w *= inv;
    vb.x *= inv; vb.y *= inv; vb.z *= inv; vb.w *= inv;

    ((float4*)p)[t]       = va;
    ((float4*)p)[t + 256] = vb;

    __half2* hp = (__half2*)(ah + row * N_ + (size_t)t * 4);
    hp[0] = __halves2half2(__float2half_rn(va.x), __float2half_rn(va.y));
    hp[1] = __halves2half2(__float2half_rn(va.z), __float2half_rn(va.w));
    __half2* hp2 = (__half2*)(ah + row * N_ + 1024 + (size_t)t * 4);
    hp2[0] = __halves2half2(__float2half_rn(vb.x), __float2half_rn(vb.y));
    hp2[1] = __halves2half2(__float2half_rn(vb.z), __float2half_rn(vb.w));
}

// ---------------------------------------------------------------------------
extern "C" void kernel_launch(void* const* d_in, const int* in_sizes, int n_in,
                              void* d_out, int out_size)
{
    const float* q  = (const float*)d_in[0];
    const float* k  = (const float*)d_in[1];
    const float* v  = (const float*)d_in[2];
    const float* Wq = (const float*)d_in[3];
    const float* Wk = (const float*)d_in[4];
    const float* Wv = (const float*)d_in[5];

    float* out  = (float*)d_out;                 // [B, N, E]
    float* attn = out + (long)B_ * N_ * E_;      // [B, N, N]

    cudaFuncSetAttribute(gemm_s, cudaFuncAttributeMaxDynamicSharedMemorySize, GEMM_SMEM_TOTAL);
    cudaFuncSetAttribute(gemm_b, cudaFuncAttributeMaxDynamicSharedMemorySize, GEMM_SMEM_TOTAL);
    cudaFuncSetAttribute(gemm_proj, cudaFuncAttributeMaxDynamicSharedMemorySize, GEMM_SMEM_TOTAL);
    cudaFuncSetAttribute(gemm_o, cudaFuncAttributeMaxDynamicSharedMemorySize, O_SMEM_TOTAL);

    __half *q16, *k16, *v16, *Wq16t, *Wk16t, *Wv16, *Gt, *tmp, *vpth, *ah;
    cudaGetSymbolAddress((void**)&q16, g_q16);
    cudaGetSymbolAddress((void**)&k16, g_k16);
    cudaGetSymbolAddress((void**)&v16, g_v16);
    cudaGetSymbolAddress((void**)&Wq16t, g_Wq16t);
    cudaGetSymbolAddress((void**)&Wk16t, g_Wk16t);
    cudaGetSymbolAddress((void**)&Wv16, g_Wv16);
    cudaGetSymbolAddress((void**)&Gt, g_Gt);
    cudaGetSymbolAddress((void**)&tmp, g_tmp);
    cudaGetSymbolAddress((void**)&vpth, g_vpth);
    cudaGetSymbolAddress((void**)&ah, g_ah);

    const float c_eq    = rsqrtf((float)D_);
    const float scale   = rsqrtf((float)E_);
    const float alpha_G = c_eq * c_eq * scale;   // 512^-1.5

    // 1) input conversions
    {
        dim3 gi(2048, 1, 3);
        conv3<<<gi, 256>>>(q, k, v, q16, k16, v16, QKV_ELEMS / 4);
    }
    // 2) weight conversions (Wq/Wk transposed for the G GEMM)
    {
        dim3 gw(256, 1, 3);
        conv_wt<<<gw, 256>>>(Wq, Wk, Wv, Wq16t, Wk16t, Wv16);
    }
    // 3) Gt[d'][d] = sum_e Wk[e][d'] * Wq[e][d] * alpha_G
    {
        dim3 gG(E_ / 128, D_ / 128, 1);
        gemm_s<<<gG, 256, GEMM_SMEM_TOTAL>>>(Wk16t, Wq16t, D_, D_, E_, alpha_G, 4, Gt);
    }
    // 4) merged: tmp = q16 @ Gt^T (z=0), vpt = v16 @ Wv16^T (z=1, transposed out)
    {
        dim3 gp(E_ / 128, (B_ * N_) / 128, 2);
        gemm_proj<<<gp, 256, GEMM_SMEM_TOTAL>>>(q16, v16, Gt, Wv16, tmp, vpth, c_eq);
    }
    // 5) dots = tmp @ k16^T -> attn region (fp32 logits), batched, fp32-acc
    {
        dim3 gd(N_ / 128, N_ / 128, B_);
        gemm_b<<<gd, 256, GEMM_SMEM_TOTAL>>>(tmp, k16, N_, N_, D_,
                                             (long)N_ * D_, (long)N_ * D_, (long)N_ * N_,
                                             1.0f, attn);
    }
    // 6) softmax (in place) + fp16 emission
    softmax_fused<<<B_ * N_, 256>>>(attn, ah);

    // 7) out = attn @ vp (vp^T stored [b][e][n]) — fp16-slab-accumulated GEMM
    {
        dim3 go(E_ / 128, N_ / 128, B_);
        gemm_o<<<go, 256, O_SMEM_TOTAL>>>(ah, vpth, N_, E_, N_,
                                          (long)N_ * N_, (long)E_ * N_, (long)N_ * E_,
                                          out);
    }
}

// round 17
// speedup vs baseline: 1.1650x; 1.1650x over previous
#include <cuda_runtime.h>
#include <cuda_fp16.h>
#include <cstdint>
#include <math.h>

// Problem constants
#define B_ 8
#define N_ 2048
#define D_ 512
#define E_ 512

static constexpr long QKV_ELEMS  = (long)B_ * N_ * D_;   // 8,388,608
static constexpr long W_ELEMS    = (long)E_ * D_;        // 262,144
static constexpr long ATTN_ELEMS = (long)B_ * N_ * N_;   // 33,554,432

// ---------------- scratch (static device arrays; allocation-guard safe) ----
__device__ __half g_q16[QKV_ELEMS], g_k16[QKV_ELEMS], g_v16[QKV_ELEMS];
__device__ __half g_Wq16t[W_ELEMS];                       // Wq^T [d][e]
__device__ __half g_Wk16t[W_ELEMS];                       // Wk^T [d][e]
__device__ __half g_Wv16[W_ELEMS];                        // Wv   [e][d]
__device__ __half g_Gt[W_ELEMS];                          // Gt[d'][d] = (Wq^T Wk)_{d,d'} * c^2 s
__device__ __half g_tmp[QKV_ELEMS];                       // tmp = q @ G'
__device__ __half g_vpth[QKV_ELEMS];                      // v-proj fp16, [b][e][n]
__device__ __half g_ah[ATTN_ELEMS];                       // fp16 logits, then fp16 probs (in place)

// ---------------- PTX helpers ----------------------------------------------
__device__ __forceinline__ uint32_t smem_to_u32(const void* p) {
    uint32_t a;
    asm("{ .reg .u64 t; cvta.to.shared.u64 t, %1; cvt.u32.u64 %0, t; }" : "=r"(a) : "l"(p));
    return a;
}

#define CP_ASYNC16(smem_u32, gptr) \
    asm volatile("cp.async.cg.shared.global [%0], [%1], 16;" :: "r"(smem_u32), "l"(gptr) : "memory")
#define CP_ASYNC_COMMIT() asm volatile("cp.async.commit_group;" ::: "memory")
#define CP_ASYNC_WAIT1()  asm volatile("cp.async.wait_group 1;" ::: "memory")

__device__ __forceinline__ void ldsm_x4(uint32_t* r, uint32_t addr) {
    asm volatile("ldmatrix.sync.aligned.m8n8.x4.shared.b16 {%0,%1,%2,%3}, [%4];"
        : "=r"(r[0]), "=r"(r[1]), "=r"(r[2]), "=r"(r[3]) : "r"(addr));
}

__device__ __forceinline__ void mma16816(float* c, const uint32_t* a, const uint32_t* b) {
    asm volatile(
        "mma.sync.aligned.m16n8k16.row.col.f32.f16.f16.f32 "
        "{%0,%1,%2,%3}, {%4,%5,%6,%7}, {%8,%9}, {%0,%1,%2,%3};"
        : "+f"(c[0]), "+f"(c[1]), "+f"(c[2]), "+f"(c[3])
        : "r"(a[0]), "r"(a[1]), "r"(a[2]), "r"(a[3]), "r"(b[0]), "r"(b[1]));
}

// ---------------------------------------------------------------------------
// fp32-acc single-product GEMM core (R13 config):
// tile 128x128, BK=32, 8 warps (64x32), 3-stage ring, 2 CTAs/SM.
// mode 0: C0 fp32 [M,N];  mode 4: C0 fp16 [M,N];  mode 2: fp16 transposed.
// ---------------------------------------------------------------------------
#define BKH 32
#define ROWH 40
#define ROWB 80
#define T_TILE_B (128 * ROWB)
#define STAGE_B (2 * T_TILE_B)
#define OFF_B (T_TILE_B)
#define NSTAGE 3
#define GEMM_SMEM_TOTAL (NSTAGE * STAGE_B)  // 61440 -> 2 CTAs/SM

__device__ __forceinline__ void gemm_core(
    const __half* __restrict__ A, const __half* __restrict__ B,
    int M, int N, int K, float alpha, int mode,
    void* __restrict__ C0, uint32_t smem_base)
{
    const int tid  = threadIdx.x;
    const int wid  = tid >> 5;
    const int lane = tid & 31;
    const int wm = wid & 1;
    const int wn = wid >> 1;

    const int m0 = blockIdx.y * 128;
    const int n0 = blockIdx.x * 128;

    float acc[4][4][4];
    #pragma unroll
    for (int i = 0; i < 4; i++)
        #pragma unroll
        for (int j = 0; j < 4; j++)
            #pragma unroll
            for (int c = 0; c < 4; c++) acc[i][j][c] = 0.0f;

    const int nslab = K / BKH;
    const int lrow = tid >> 2;
    const int lch  = tid & 3;

    auto load_slab = [&](int s) {
        const long koff = (long)s * BKH + lch * 8;
        const uint32_t st = smem_base + (uint32_t)(s % NSTAGE) * STAGE_B;
        const uint32_t so = (uint32_t)(lrow * ROWB + lch * 16);
        #pragma unroll
        for (int i = 0; i < 2; i++) {
            const int r = lrow + 64 * i;
            const long ga = (long)(m0 + r) * K + koff;
            const long gb = (long)(n0 + r) * K + koff;
            const uint32_t ro = so + (uint32_t)i * (64 * ROWB);
            CP_ASYNC16(st +         ro, A + ga);
            CP_ASYNC16(st + OFF_B + ro, B + gb);
        }
    };

    load_slab(0); CP_ASYNC_COMMIT();
    if (nslab > 1) load_slab(1);
    CP_ASYNC_COMMIT();

    const int am = lane & 15;
    const int ac = (lane >> 4) << 3;
    const int bn = ((lane >> 4) << 3) + (lane & 7);
    const int bc = ((lane >> 3) & 1) << 3;

    for (int s = 0; s < nslab; s++) {
        CP_ASYNC_WAIT1();
        __syncthreads();

        const uint32_t st = smem_base + (uint32_t)(s % NSTAGE) * STAGE_B;
        #pragma unroll
        for (int k16 = 0; k16 < 2; k16++) {
            uint32_t ra[4][4];
            #pragma unroll
            for (int mi = 0; mi < 4; mi++) {
                const uint32_t ao =
                    (uint32_t)((wm * 64 + mi * 16 + am) * ROWH + k16 * 16 + ac) * 2;
                ldsm_x4(ra[mi], st + ao);
            }
            uint32_t th[2][4];
            const uint32_t bbase =
                (uint32_t)((wn * 32 + bn) * ROWH + k16 * 16 + bc) * 2;
            ldsm_x4(th[0], st + OFF_B + bbase);

            if (k16 == 0) {
                if (s + 2 < nslab) load_slab(s + 2);
                CP_ASYNC_COMMIT();
            }

            #pragma unroll
            for (int pair = 0; pair < 2; pair++) {
                const int cur = pair & 1;
                if (pair < 1) {
                    const uint32_t bo = bbase + (uint32_t)(16 * ROWH) * 2;
                    ldsm_x4(th[cur ^ 1], st + OFF_B + bo);
                }
                #pragma unroll
                for (int nj = 0; nj < 2; nj++) {
                    const uint32_t bh2[2] = { th[cur][nj * 2], th[cur][nj * 2 + 1] };
                    #pragma unroll
                    for (int mi = 0; mi < 4; mi++)
                        mma16816(acc[mi][pair * 2 + nj], ra[mi], bh2);
                }
            }
        }
    }

    const int rq = lane >> 2;
    const int cq = (lane & 3) * 2;
    #pragma unroll
    for (int mi = 0; mi < 4; mi++) {
        #pragma unroll
        for (int ni = 0; ni < 4; ni++) {
            const int mA = m0 + wm * 64 + mi * 16 + rq;
            const int mB = mA + 8;
            const int n  = n0 + wn * 32 + ni * 8 + cq;
            const float v0 = acc[mi][ni][0] * alpha;
            const float v1 = acc[mi][ni][1] * alpha;
            const float v2 = acc[mi][ni][2] * alpha;
            const float v3 = acc[mi][ni][3] * alpha;
            if (mode == 0) {
                float* Cf = (float*)C0;
                *(float2*)(Cf + (size_t)mA * N + n) = make_float2(v0, v1);
                *(float2*)(Cf + (size_t)mB * N + n) = make_float2(v2, v3);
            } else if (mode == 4) {
                *(__half2*)((__half*)C0 + (size_t)mA * N + n) =
                    __halves2half2(__float2half_rn(v0), __float2half_rn(v1));
                *(__half2*)((__half*)C0 + (size_t)mB * N + n) =
                    __halves2half2(__float2half_rn(v2), __float2half_rn(v3));
            } else {
                const float vv[4] = { v0, v1, v2, v3 };
                #pragma unroll
                for (int e = 0; e < 4; e++) {
                    const int m = (e < 2) ? mA : mB;
                    const int nn2 = n + (e & 1);
                    const int bi = m >> 11;
                    const int mm = m & (N_ - 1);
                    const size_t idx = ((size_t)bi * E_ + nn2) * N_ + mm;
                    ((__half*)C0)[idx] = __float2half_rn(vv[e]);
                }
            }
        }
    }
}

__global__ __launch_bounds__(256, 2) void gemm_s(
    const __half* __restrict__ A, const __half* __restrict__ B,
    int M, int N, int K, float alpha, int mode, void* __restrict__ C0)
{
    extern __shared__ char smem[];
    gemm_core(A, B, M, N, K, alpha, mode, C0, smem_to_u32(smem));
}

// batched GEMM: mode 0 (fp32 out) or mode 4 (fp16 out), z batches via strides
__global__ __launch_bounds__(256, 2) void gemm_b(
    const __half* __restrict__ A, const __half* __restrict__ B,
    int M, int N, int K, long sA, long sB, long sC,
    float alpha, int mode, void* __restrict__ C0)
{
    extern __shared__ char smem[];
    const int z = blockIdx.z;
    void* C = (mode == 0) ? (void*)((float*)C0 + (size_t)z * sC)
                          : (void*)((__half*)C0 + (size_t)z * sC);
    gemm_core(A + (long)z * sA, B + (long)z * sB, M, N, K, alpha, mode,
              C, smem_to_u32(smem));
}

// merged: z = 0 (tmp = q16 @ Gt^T, mode 4), z = 1 (v-proj, mode 2 transposed)
__global__ __launch_bounds__(256, 2) void gemm_proj(
    const __half* __restrict__ q16, const __half* __restrict__ v16,
    const __half* __restrict__ Gt, const __half* __restrict__ Wv,
    __half* __restrict__ tmp, __half* __restrict__ vpth, float c_eq)
{
    extern __shared__ char smem[];
    const int z = blockIdx.z;
    const __half* A = (z == 0) ? q16 : v16;
    const __half* B = (z == 0) ? Gt  : Wv;
    void* C = (z == 0) ? (void*)tmp : (void*)vpth;
    const int mode = (z == 0) ? 4 : 2;
    const float alpha = (z == 0) ? 1.0f : c_eq;
    gemm_core(A, B, B_ * N_, E_, D_, alpha, mode, C, smem_to_u32(smem));
}

// ---------------------------------------------------------------------------
// elementwise conversions
// ---------------------------------------------------------------------------
__global__ __launch_bounds__(256) void conv3(
    const float* __restrict__ x0, const float* __restrict__ x1, const float* __restrict__ x2,
    __half* __restrict__ h0, __half* __restrict__ h1, __half* __restrict__ h2, long n4)
{
    const int zz = blockIdx.z;
    const float* x = (zz == 0) ? x0 : (zz == 1) ? x1 : x2;
    __half* h = (zz == 0) ? h0 : (zz == 1) ? h1 : h2;
    for (long i = blockIdx.x * 256 + threadIdx.x; i < n4; i += (long)gridDim.x * 256) {
        float4 vv = ((const float4*)x)[i];
        __half2* hp = (__half2*)(h + i * 4);
        hp[0] = __halves2half2(__float2half_rn(vv.x), __float2half_rn(vv.y));
        hp[1] = __halves2half2(__float2half_rn(vv.z), __float2half_rn(vv.w));
    }
}

__global__ __launch_bounds__(256) void conv_wt(
    const float* __restrict__ Wq, const float* __restrict__ Wk, const float* __restrict__ Wv,
    __half* __restrict__ Wqt, __half* __restrict__ Wkt, __half* __restrict__ Wv16)
{
    const int zz = blockIdx.z;
    const float* x = (zz == 0) ? Wq : (zz == 1) ? Wk : Wv;
    __half* o = (zz == 0) ? Wqt : (zz == 1) ? Wkt : Wv16;
    for (long i = blockIdx.x * 256 + threadIdx.x; i < W_ELEMS; i += (long)gridDim.x * 256) {
        const int e = (int)(i >> 9);
        const int d = (int)(i & 511);
        const __half h = __float2half_rn(x[i]);
        if (zz < 2) o[(size_t)d * E_ + e] = h;
        else        o[i] = h;
    }
}

// ---------------------------------------------------------------------------
// fused softmax: reads fp16 logits (in place in ah), computes in fp32,
// writes fp32 attn (d_out region) + fp16 probs back to ah. One block per row.
// ---------------------------------------------------------------------------
__global__ __launch_bounds__(256) void softmax_fused(
    __half* __restrict__ ah, float* __restrict__ attn)
{
    const size_t row = blockIdx.x;
    __half* p16 = ah + row * N_;
    float* pf = attn + row * N_;
    const int t = threadIdx.x;
    __shared__ float red[8];

    // load 8 fp16 logits per thread (one uint4)
    const uint4 raw = ((const uint4*)p16)[t];
    const __half2* h2 = (const __half2*)&raw;
    float x[8];
    {
        float2 f0 = __half22float2(h2[0]);
        float2 f1 = __half22float2(h2[1]);
        float2 f2 = __half22float2(h2[2]);
        float2 f3 = __half22float2(h2[3]);
        x[0] = f0.x; x[1] = f0.y; x[2] = f1.x; x[3] = f1.y;
        x[4] = f2.x; x[5] = f2.y; x[6] = f3.x; x[7] = f3.y;
    }

    float vmax = x[0];
    #pragma unroll
    for (int i = 1; i < 8; i++) vmax = fmaxf(vmax, x[i]);
    #pragma unroll
    for (int o = 16; o > 0; o >>= 1) vmax = fmaxf(vmax, __shfl_xor_sync(0xFFFFFFFF, vmax, o));
    if ((t & 31) == 0) red[t >> 5] = vmax;
    __syncthreads();
    const float m = fmaxf(fmaxf(fmaxf(red[0], red[1]), fmaxf(red[2], red[3])),
                          fmaxf(fmaxf(red[4], red[5]), fmaxf(red[6], red[7])));
    __syncthreads();

    float sum = 0.0f;
    #pragma unroll
    for (int i = 0; i < 8; i++) { x[i] = __expf(x[i] - m); sum += x[i]; }
    #pragma unroll
    for (int o = 16; o > 0; o >>= 1) sum += __shfl_xor_sync(0xFFFFFFFF, sum, o);
    if ((t & 31) == 0) red[t >> 5] = sum;
    __syncthreads();
    const float inv = 1.0f / (red[0] + red[1] + red[2] + red[3] + red[4] + red[5] + red[6] + red[7]);

    #pragma unroll
    for (int i = 0; i < 8; i++) x[i] *= inv;

    // fp32 attn output (two float4 per thread)
    float4* pf4 = (float4*)(pf + (size_t)t * 8);
    pf4[0] = make_float4(x[0], x[1], x[2], x[3]);
    pf4[1] = make_float4(x[4], x[5], x[6], x[7]);

    // fp16 probs back in place (one uint4)
    uint4 outh;
    __half2* oh = (__half2*)&outh;
    oh[0] = __halves2half2(__float2half_rn(x[0]), __float2half_rn(x[1]));
    oh[1] = __halves2half2(__float2half_rn(x[2]), __float2half_rn(x[3]));
    oh[2] = __halves2half2(__float2half_rn(x[4]), __float2half_rn(x[5]));
    oh[3] = __halves2half2(__float2half_rn(x[6]), __float2half_rn(x[7]));
    ((uint4*)p16)[t] = outh;
}

// ---------------------------------------------------------------------------
extern "C" void kernel_launch(void* const* d_in, const int* in_sizes, int n_in,
                              void* d_out, int out_size)
{
    const float* q  = (const float*)d_in[0];
    const float* k  = (const float*)d_in[1];
    const float* v  = (const float*)d_in[2];
    const float* Wq = (const float*)d_in[3];
    const float* Wk = (const float*)d_in[4];
    const float* Wv = (const float*)d_in[5];

    float* out  = (float*)d_out;                 // [B, N, E]
    float* attn = out + (long)B_ * N_ * E_;      // [B, N, N]

    cudaFuncSetAttribute(gemm_s, cudaFuncAttributeMaxDynamicSharedMemorySize, GEMM_SMEM_TOTAL);
    cudaFuncSetAttribute(gemm_b, cudaFuncAttributeMaxDynamicSharedMemorySize, GEMM_SMEM_TOTAL);
    cudaFuncSetAttribute(gemm_proj, cudaFuncAttributeMaxDynamicSharedMemorySize, GEMM_SMEM_TOTAL);

    __half *q16, *k16, *v16, *Wq16t, *Wk16t, *Wv16, *Gt, *tmp, *vpth, *ah;
    cudaGetSymbolAddress((void**)&q16, g_q16);
    cudaGetSymbolAddress((void**)&k16, g_k16);
    cudaGetSymbolAddress((void**)&v16, g_v16);
    cudaGetSymbolAddress((void**)&Wq16t, g_Wq16t);
    cudaGetSymbolAddress((void**)&Wk16t, g_Wk16t);
    cudaGetSymbolAddress((void**)&Wv16, g_Wv16);
    cudaGetSymbolAddress((void**)&Gt, g_Gt);
    cudaGetSymbolAddress((void**)&tmp, g_tmp);
    cudaGetSymbolAddress((void**)&vpth, g_vpth);
    cudaGetSymbolAddress((void**)&ah, g_ah);

    const float c_eq    = rsqrtf((float)D_);
    const float scale   = rsqrtf((float)E_);
    const float alpha_G = c_eq * c_eq * scale;   // 512^-1.5

    // 1) input conversions
    {
        dim3 gi(2048, 1, 3);
        conv3<<<gi, 256>>>(q, k, v, q16, k16, v16, QKV_ELEMS / 4);
    }
    // 2) weight conversions (Wq/Wk transposed for the G GEMM)
    {
        dim3 gw(256, 1, 3);
        conv_wt<<<gw, 256>>>(Wq, Wk, Wv, Wq16t, Wk16t, Wv16);
    }
    // 3) Gt[d'][d] = sum_e Wk[e][d'] * Wq[e][d] * alpha_G
    {
        dim3 gG(E_ / 128, D_ / 128, 1);
        gemm_s<<<gG, 256, GEMM_SMEM_TOTAL>>>(Wk16t, Wq16t, D_, D_, E_, alpha_G, 4, Gt);
    }
    // 4) merged: tmp = q16 @ Gt^T (z=0), vpt = v16 @ Wv16^T (z=1, transposed out)
    {
        dim3 gp(E_ / 128, (B_ * N_) / 128, 2);
        gemm_proj<<<gp, 256, GEMM_SMEM_TOTAL>>>(q16, v16, Gt, Wv16, tmp, vpth, c_eq);
    }
    // 5) logits = tmp @ k16^T -> fp16 scratch ah, batched
    {
        dim3 gd(N_ / 128, N_ / 128, B_);
        gemm_b<<<gd, 256, GEMM_SMEM_TOTAL>>>(tmp, k16, N_, N_, D_,
                                             (long)N_ * D_, (long)N_ * D_, (long)N_ * N_,
                                             1.0f, 4, ah);
    }
    // 6) softmax: fp16 logits -> fp32 attn (d_out) + fp16 probs (in place)
    softmax_fused<<<B_ * N_, 256>>>(ah, attn);

    // 7) out = probs @ vp (vp^T stored [b][e][n]), fp32-acc GEMM
    {
        dim3 go(E_ / 128, N_ / 128, B_);
        gemm_b<<<go, 256, GEMM_SMEM_TOTAL>>>(ah, vpth, N_, E_, N_,
                                             (long)N_ * N_, (long)E_ * N_, (long)N_ * E_,
                                             1.0f, 0, out);
    }
}